// round 1
// baseline (speedup 1.0000x reference)
#include <cuda_runtime.h>
#include <cuda_bf16.h>

// Problem constants (from reference): B=16384, D=32, G=6, ND=8, deep_in=200, H1=128, H2=64
#define MAXB 16384
#define DEEP_IN 200

// Scratch: activation matrix [B,200] and (first+second order) base term [B].
// Static __device__ arrays (no allocation allowed).
__device__ float g_xs[(size_t)MAXB * DEEP_IN];
__device__ float g_base[MAXB];

// ---------------------------------------------------------------------------
// Kernel 1: one warp per row. Gathers embeddings, builds deep_in row in g_xs,
// computes FM first order + second order into g_base.
// lane = embedding dim (D=32 == warpSize).
// ---------------------------------------------------------------------------
__global__ void deepfm_gather_kernel(
    const int* __restrict__ uid, const int* __restrict__ iid,
    const int* __restrict__ gen, const int* __restrict__ age,
    const int* __restrict__ occ,
    const int* __restrict__ gids, const float* __restrict__ gmask,
    const float* __restrict__ dense,
    const float* __restrict__ fo_user, const float* __restrict__ fo_item,
    const float* __restrict__ fo_gender, const float* __restrict__ fo_age,
    const float* __restrict__ fo_occ, const float* __restrict__ fo_genre,
    const float* __restrict__ emb_user, const float* __restrict__ emb_item,
    const float* __restrict__ emb_gender, const float* __restrict__ emb_age,
    const float* __restrict__ emb_occ, const float* __restrict__ emb_genre,
    const float* __restrict__ dense_W, const float* __restrict__ dense_b,
    int B)
{
    int warp = (blockIdx.x * blockDim.x + threadIdx.x) >> 5;
    int lane = threadIdx.x & 31;
    if (warp >= B) return;
    int r = warp;

    int u  = uid[r];
    int it = iid[r];
    int g  = gen[r];
    int a  = age[r];
    int o  = occ[r];

    float xu = emb_user  [u  * 32 + lane];
    float xi = emb_item  [it * 32 + lane];
    float xg = emb_gender[g  * 32 + lane];
    float xa = emb_age   [a  * 32 + lane];
    float xo = emb_occ   [o  * 32 + lane];

    float gsum = 0.f, msum = 0.f, fsum = 0.f;
#pragma unroll
    for (int k = 0; k < 6; k++) {
        int   gid = gids [r * 6 + k];
        float m   = gmask[r * 6 + k];
        gsum += m * emb_genre[gid * 32 + lane];
        msum += m;
        fsum += m * fo_genre[gid];
    }
    float denom = fmaxf(msum, 1.0f);
    float xge = gsum / denom;

    float* xs = g_xs + (size_t)r * DEEP_IN;
    xs[lane]        = xu;
    xs[32 + lane]   = xi;
    xs[64 + lane]   = xg;
    xs[96 + lane]   = xa;
    xs[128 + lane]  = xo;
    xs[160 + lane]  = xge;
    float dv = 0.f;
    if (lane < 8) {
        dv = dense[r * 8 + lane];
        xs[192 + lane] = dv;
    }

    // FM second order: lane holds dim d over the 6 fields
    float s  = xu + xi + xg + xa + xo + xge;
    float sq = xu*xu + xi*xi + xg*xg + xa*xa + xo*xo + xge*xge;
    float part = 0.5f * (s * s - sq);
#pragma unroll
    for (int off = 16; off; off >>= 1)
        part += __shfl_xor_sync(0xffffffffu, part, off);

    // dense linear dot (lanes 0..7 hold dense features)
    float dp = (lane < 8) ? dv * dense_W[lane] : 0.f;
#pragma unroll
    for (int off = 16; off; off >>= 1)
        dp += __shfl_xor_sync(0xffffffffu, dp, off);

    if (lane == 0) {
        float first = fo_user[u] + fo_item[it] + fo_gender[g] + fo_age[a]
                    + fo_occ[o] + fsum / denom + dp + dense_b[0];
        g_base[r] = first + part;
    }
}

// ---------------------------------------------------------------------------
// Kernel 2: persistent register-blocked MLP.
// 256 threads. Thread t owns:
//   layer1: output j1 = t&127, k-half h = t>>7 -> 100 W1 weights in registers
//   layer2: output j2 = t&63,  k-quarter q = t>>6 -> 32 W2 weights in registers
// Tiles of 8 rows; activations broadcast from shared via LDS.128 (1 wavefront).
// Partial sums combined through padded shared buffers.
// ---------------------------------------------------------------------------
__global__ __launch_bounds__(256, 1) void deepfm_mlp_kernel(
    const float* __restrict__ W1, const float* __restrict__ b1,
    const float* __restrict__ W2, const float* __restrict__ b2,
    const float* __restrict__ Wout, const float* __restrict__ bout,
    float* __restrict__ out, int B)
{
    __shared__ __align__(16) float xss[8 * DEEP_IN];  // 8 rows x 200
    __shared__ float sp1[128 * 9];                    // layer1 partner partials (padded)
    __shared__ __align__(16) float hs1[8 * 128];      // relu(h1) row-major [r][j]
    __shared__ float sp2[3 * 64 * 9];                 // layer2 partials (padded)
    __shared__ float hs2[8 * 64];                     // relu(h2)
    __shared__ float wout_s[64];
    __shared__ float base_s[8];

    const int t    = threadIdx.x;
    const int j1   = t & 127;
    const int h    = t >> 7;        // 0 or 1
    const int j2   = t & 63;
    const int q    = t >> 6;        // 0..3
    const int wrp  = t >> 5;
    const int lane = t & 31;

    // Load weights into registers (streamed once per persistent CTA)
    float w1[100];
#pragma unroll
    for (int k = 0; k < 100; k++) w1[k] = W1[j1 * DEEP_IN + h * 100 + k];
    float w2[32];
#pragma unroll
    for (int k = 0; k < 32; k++) w2[k] = W2[j2 * 128 + q * 32 + k];
    const float b1v = b1[j1];
    const float b2v = b2[j2];
    if (t < 64) wout_s[t] = Wout[t];
    const float boutv = bout[0];

    const int nTiles = (B + 7) >> 3;
    for (int tile = blockIdx.x; tile < nTiles; tile += gridDim.x) {
        const int base = tile * 8;

        __syncthreads();  // protect shared buffers from previous iteration readers
        // Stage activation tile (8 rows x 200) coalesced from gmem scratch
        {
            const float* src = g_xs + (size_t)base * DEEP_IN;
            int limit = (B - base) * DEEP_IN;
            if (limit > 8 * DEEP_IN) limit = 8 * DEEP_IN;
            for (int i = t; i < limit; i += 256) xss[i] = src[i];
        }
        if (t < 8 && base + t < B) base_s[t] = g_base[base + t];
        __syncthreads();

        // ---- Layer 1: h1 = relu(W1 @ x + b1) ----
        float acc[8];
#pragma unroll
        for (int r = 0; r < 8; r++) acc[r] = 0.f;
#pragma unroll
        for (int kk = 0; kk < 100; kk += 4) {
#pragma unroll
            for (int r = 0; r < 8; r++) {
                const float4 xv = *(const float4*)&xss[r * DEEP_IN + h * 100 + kk];
                acc[r] = fmaf(w1[kk + 0], xv.x, acc[r]);
                acc[r] = fmaf(w1[kk + 1], xv.y, acc[r]);
                acc[r] = fmaf(w1[kk + 2], xv.z, acc[r]);
                acc[r] = fmaf(w1[kk + 3], xv.w, acc[r]);
            }
        }
        if (h == 1) {
#pragma unroll
            for (int r = 0; r < 8; r++) sp1[j1 * 9 + r] = acc[r];
        }
        __syncthreads();
        if (h == 0) {
#pragma unroll
            for (int r = 0; r < 8; r++) {
                float v = acc[r] + sp1[j1 * 9 + r] + b1v;
                hs1[r * 128 + j1] = fmaxf(v, 0.f);
            }
        }
        __syncthreads();

        // ---- Layer 2: h2 = relu(W2 @ h1 + b2) ----
        float acc2[8];
#pragma unroll
        for (int r = 0; r < 8; r++) acc2[r] = 0.f;
#pragma unroll
        for (int kk = 0; kk < 32; kk += 4) {
#pragma unroll
            for (int r = 0; r < 8; r++) {
                const float4 hv = *(const float4*)&hs1[r * 128 + q * 32 + kk];
                acc2[r] = fmaf(w2[kk + 0], hv.x, acc2[r]);
                acc2[r] = fmaf(w2[kk + 1], hv.y, acc2[r]);
                acc2[r] = fmaf(w2[kk + 2], hv.z, acc2[r]);
                acc2[r] = fmaf(w2[kk + 3], hv.w, acc2[r]);
            }
        }
        if (q > 0) {
#pragma unroll
            for (int r = 0; r < 8; r++) sp2[(q - 1) * 576 + j2 * 9 + r] = acc2[r];
        }
        __syncthreads();
        if (q == 0) {
#pragma unroll
            for (int r = 0; r < 8; r++) {
                float v = acc2[r] + sp2[j2 * 9 + r] + sp2[576 + j2 * 9 + r]
                        + sp2[1152 + j2 * 9 + r] + b2v;
                hs2[r * 64 + j2] = fmaxf(v, 0.f);
            }
        }
        __syncthreads();

        // ---- Output: warp w handles row w ----
        {
            float p = wout_s[lane]      * hs2[wrp * 64 + lane]
                    + wout_s[32 + lane] * hs2[wrp * 64 + 32 + lane];
#pragma unroll
            for (int off = 16; off; off >>= 1)
                p += __shfl_xor_sync(0xffffffffu, p, off);
            if (lane == 0 && base + wrp < B)
                out[base + wrp] = base_s[wrp] + p + boutv;
        }
    }
}

// ---------------------------------------------------------------------------
// Launch
// ---------------------------------------------------------------------------
extern "C" void kernel_launch(void* const* d_in, const int* in_sizes, int n_in,
                              void* d_out, int out_size)
{
    const int*   uid      = (const int*)  d_in[0];
    const int*   iid      = (const int*)  d_in[1];
    const int*   gen      = (const int*)  d_in[2];
    const int*   age      = (const int*)  d_in[3];
    const int*   occ      = (const int*)  d_in[4];
    const int*   gids     = (const int*)  d_in[5];
    const float* gmask    = (const float*)d_in[6];
    const float* dense    = (const float*)d_in[7];
    const float* fo_user  = (const float*)d_in[8];
    const float* fo_item  = (const float*)d_in[9];
    const float* fo_gender= (const float*)d_in[10];
    const float* fo_age   = (const float*)d_in[11];
    const float* fo_occ   = (const float*)d_in[12];
    const float* fo_genre = (const float*)d_in[13];
    const float* emb_user = (const float*)d_in[14];
    const float* emb_item = (const float*)d_in[15];
    const float* emb_gender=(const float*)d_in[16];
    const float* emb_age  = (const float*)d_in[17];
    const float* emb_occ  = (const float*)d_in[18];
    const float* emb_genre= (const float*)d_in[19];
    const float* dense_W  = (const float*)d_in[20];
    const float* dense_b  = (const float*)d_in[21];
    const float* W1       = (const float*)d_in[22];
    const float* b1       = (const float*)d_in[23];
    const float* W2       = (const float*)d_in[24];
    const float* b2       = (const float*)d_in[25];
    const float* Wout     = (const float*)d_in[26];
    const float* bout     = (const float*)d_in[27];
    float*       out      = (float*)d_out;

    const int B = in_sizes[0];

    // Kernel 1: one warp per row
    {
        int threads = 256;
        int warpsPerBlock = threads / 32;
        int blocks = (B + warpsPerBlock - 1) / warpsPerBlock;
        deepfm_gather_kernel<<<blocks, threads>>>(
            uid, iid, gen, age, occ, gids, gmask, dense,
            fo_user, fo_item, fo_gender, fo_age, fo_occ, fo_genre,
            emb_user, emb_item, emb_gender, emb_age, emb_occ, emb_genre,
            dense_W, dense_b, B);
    }

    // Kernel 2: persistent MLP, one CTA per SM
    {
        int sm = 148;
        cudaDeviceGetAttribute(&sm, cudaDevAttrMultiProcessorCount, 0);
        int nTiles = (B + 7) >> 3;
        int blocks = sm < nTiles ? sm : nTiles;
        deepfm_mlp_kernel<<<blocks, 256>>>(W1, b1, W2, b2, Wout, bout, out, B);
    }
}

// round 2
// speedup vs baseline: 1.2943x; 1.2943x over previous
#include <cuda_runtime.h>
#include <cuda_bf16.h>

#define DEEP_IN 200
#define TILE_R  128

// Dynamic shared layout (floats):
//   Xs  : [128][200]            off 0       (25600)
//   h1s : [128 j][132 r]        off 25600   (16896)
//   Wbuf: W1 chunk [40][132] (5280) or W2s [128][68] (8704) -> region 8704
#define OFF_XS   0
#define OFF_H1S  25600
#define OFF_WB   42496
#define SMEM_FLOATS 51200   // 204800 bytes

__global__ __launch_bounds__(256, 1) void deepfm_fused_kernel(
    const int* __restrict__ uid, const int* __restrict__ iid,
    const int* __restrict__ gen, const int* __restrict__ age,
    const int* __restrict__ occ,
    const int* __restrict__ gids, const float* __restrict__ gmask,
    const float* __restrict__ dense,
    const float* __restrict__ fo_user, const float* __restrict__ fo_item,
    const float* __restrict__ fo_gender, const float* __restrict__ fo_age,
    const float* __restrict__ fo_occ, const float* __restrict__ fo_genre,
    const float* __restrict__ emb_user, const float* __restrict__ emb_item,
    const float* __restrict__ emb_gender, const float* __restrict__ emb_age,
    const float* __restrict__ emb_occ, const float* __restrict__ emb_genre,
    const float* __restrict__ dense_W, const float* __restrict__ dense_b,
    const float* __restrict__ W1, const float* __restrict__ b1,
    const float* __restrict__ W2, const float* __restrict__ b2,
    const float* __restrict__ Wout, const float* __restrict__ bout,
    float* __restrict__ out, int B)
{
    extern __shared__ float sm[];
    __shared__ float base_s[TILE_R];
    __shared__ float wout_s[64];

    const int t    = threadIdx.x;
    const int tx   = t & 15;
    const int ty   = t >> 4;
    const int lane = t & 31;
    const int wrp  = t >> 5;
    const int rowbase = blockIdx.x * TILE_R;

    if (t < 64) wout_s[t] = Wout[t];

    // ================= Gather prologue: warp w handles rows w*16..w*16+15 ====
    for (int i = 0; i < 16; i++) {
        const int rl = wrp * 16 + i;
        const int r  = rowbase + rl;
        if (r >= B) break;

        const int u  = uid[r];
        const int it = iid[r];
        const int g  = gen[r];
        const int a  = age[r];
        const int o  = occ[r];

        const float xu = emb_user  [u  * 32 + lane];
        const float xi = emb_item  [it * 32 + lane];
        const float xg = emb_gender[g  * 32 + lane];
        const float xa = emb_age   [a  * 32 + lane];
        const float xo = emb_occ   [o  * 32 + lane];

        float gsum = 0.f, msum = 0.f, fsum = 0.f;
#pragma unroll
        for (int k = 0; k < 6; k++) {
            const int   gid = gids [r * 6 + k];
            const float m   = gmask[r * 6 + k];
            gsum += m * emb_genre[gid * 32 + lane];
            msum += m;
            fsum += m * fo_genre[gid];
        }
        const float denom = fmaxf(msum, 1.0f);
        const float xge = gsum / denom;

        float* xs = sm + OFF_XS + rl * DEEP_IN;
        xs[lane]       = xu;
        xs[32 + lane]  = xi;
        xs[64 + lane]  = xg;
        xs[96 + lane]  = xa;
        xs[128 + lane] = xo;
        xs[160 + lane] = xge;
        float dv = 0.f;
        if (lane < 8) {
            dv = dense[r * 8 + lane];
            xs[192 + lane] = dv;
        }

        // FM second order (lane = dim)
        const float s  = xu + xi + xg + xa + xo + xge;
        const float sq = xu*xu + xi*xi + xg*xg + xa*xa + xo*xo + xge*xge;
        float part = 0.5f * (s * s - sq);
#pragma unroll
        for (int off = 16; off; off >>= 1)
            part += __shfl_xor_sync(0xffffffffu, part, off);

        float dp = (lane < 8) ? dv * dense_W[lane] : 0.f;
#pragma unroll
        for (int off = 16; off; off >>= 1)
            dp += __shfl_xor_sync(0xffffffffu, dp, off);

        if (lane == 0) {
            base_s[rl] = fo_user[u] + fo_item[it] + fo_gender[g] + fo_age[a]
                       + fo_occ[o] + fsum / denom + dp + dense_b[0] + part;
        }
    }
    __syncthreads();

    // Row / col ownership (split 4+4 at distance 64 for conflict-free LDS.128)
    int R[8], C[8];
#pragma unroll
    for (int p = 0; p < 8; p++) R[p] = ty * 4 + (p & 3) + (p >> 2) * 64;
#pragma unroll
    for (int q = 0; q < 8; q++) C[q] = tx * 4 + (q & 3) + (q >> 2) * 64;

    // ================= Layer 1: h1 = relu(X @ W1^T + b1) =====================
    float acc[8][8];
#pragma unroll
    for (int p = 0; p < 8; p++)
#pragma unroll
        for (int q = 0; q < 8; q++) acc[p][q] = 0.f;

    for (int c = 0; c < 5; c++) {
        const int k0 = c * 40;
        // Stage W1 chunk transposed: W1s[i][j] = W1[j][k0+i]
        {
            const int j    = t >> 1;
            const int half = t & 1;
            const float* src = W1 + j * DEEP_IN + k0 + half * 20;
            float* dst = sm + OFF_WB;
#pragma unroll
            for (int s5 = 0; s5 < 5; s5++) {
                const float4 v = *(const float4*)(src + s5 * 4);
                const int i0 = half * 20 + s5 * 4;
                dst[(i0 + 0) * 132 + j] = v.x;
                dst[(i0 + 1) * 132 + j] = v.y;
                dst[(i0 + 2) * 132 + j] = v.z;
                dst[(i0 + 3) * 132 + j] = v.w;
            }
        }
        __syncthreads();

#pragma unroll 2
        for (int i = 0; i < 40; i++) {
            const int k = k0 + i;
            float av[8];
#pragma unroll
            for (int p = 0; p < 8; p++)
                av[p] = sm[OFF_XS + R[p] * DEEP_IN + k];
            const float4 bl = *(const float4*)&sm[OFF_WB + i * 132 + tx * 4];
            const float4 bh = *(const float4*)&sm[OFF_WB + i * 132 + 64 + tx * 4];
            const float bv[8] = {bl.x, bl.y, bl.z, bl.w, bh.x, bh.y, bh.z, bh.w};
#pragma unroll
            for (int p = 0; p < 8; p++)
#pragma unroll
                for (int q = 0; q < 8; q++)
                    acc[p][q] = fmaf(av[p], bv[q], acc[p][q]);
        }
        __syncthreads();
    }

    // Writeback h1 (k-major for layer2): h1s[j][r]
    {
        float b1v[8];
#pragma unroll
        for (int q = 0; q < 8; q++) b1v[q] = b1[C[q]];
#pragma unroll
        for (int p = 0; p < 8; p++)
#pragma unroll
            for (int q = 0; q < 8; q++)
                sm[OFF_H1S + C[q] * 132 + R[p]] = fmaxf(acc[p][q] + b1v[q], 0.f);
    }
    __syncthreads();

    // Stage W2 transposed: W2s[k][j] = W2[j][k]
    {
        const int j  = t >> 2;
        const int q4 = t & 3;
        const float* src = W2 + j * 128 + q4 * 32;
        float* dst = sm + OFF_WB;
#pragma unroll
        for (int s8 = 0; s8 < 8; s8++) {
            const float4 v = *(const float4*)(src + s8 * 4);
            const int k = q4 * 32 + s8 * 4;
            dst[(k + 0) * 68 + j] = v.x;
            dst[(k + 1) * 68 + j] = v.y;
            dst[(k + 2) * 68 + j] = v.z;
            dst[(k + 3) * 68 + j] = v.w;
        }
    }
    __syncthreads();

    // ================= Layer 2: h2 = relu(h1 @ W2^T + b2) ====================
    int C2[4];
#pragma unroll
    for (int q = 0; q < 4; q++) C2[q] = tx * 2 + (q & 1) + (q >> 1) * 32;

    float acc2[8][4];
#pragma unroll
    for (int p = 0; p < 8; p++)
#pragma unroll
        for (int q = 0; q < 4; q++) acc2[p][q] = 0.f;

#pragma unroll 4
    for (int k = 0; k < 128; k++) {
        float av[8];
#pragma unroll
        for (int p = 0; p < 8; p++)
            av[p] = sm[OFF_H1S + k * 132 + R[p]];
        const float2 w0 = *(const float2*)&sm[OFF_WB + k * 68 + tx * 2];
        const float2 w1v = *(const float2*)&sm[OFF_WB + k * 68 + 32 + tx * 2];
        const float bv[4] = {w0.x, w0.y, w1v.x, w1v.y};
#pragma unroll
        for (int p = 0; p < 8; p++)
#pragma unroll
            for (int q = 0; q < 4; q++)
                acc2[p][q] = fmaf(av[p], bv[q], acc2[p][q]);
    }

    // ================= Output: out = base + h2 @ Wout + bout ================
    {
        float b2v[4];
#pragma unroll
        for (int q = 0; q < 4; q++) b2v[q] = b2[C2[q]];
        const float boutv = bout[0];
#pragma unroll
        for (int p = 0; p < 8; p++) {
            float part = 0.f;
#pragma unroll
            for (int q = 0; q < 4; q++)
                part += fmaxf(acc2[p][q] + b2v[q], 0.f) * wout_s[C2[q]];
            // reduce over the 16 tx lanes (xor<16 stays within half-warp group)
#pragma unroll
            for (int off = 8; off; off >>= 1)
                part += __shfl_xor_sync(0xffffffffu, part, off);
            if (tx == 0) {
                const int r = rowbase + R[p];
                if (r < B) out[r] = base_s[R[p]] + part + boutv;
            }
        }
    }
}

// ---------------------------------------------------------------------------
extern "C" void kernel_launch(void* const* d_in, const int* in_sizes, int n_in,
                              void* d_out, int out_size)
{
    const int*   uid      = (const int*)  d_in[0];
    const int*   iid      = (const int*)  d_in[1];
    const int*   gen      = (const int*)  d_in[2];
    const int*   age      = (const int*)  d_in[3];
    const int*   occ      = (const int*)  d_in[4];
    const int*   gids     = (const int*)  d_in[5];
    const float* gmask    = (const float*)d_in[6];
    const float* dense    = (const float*)d_in[7];
    const float* fo_user  = (const float*)d_in[8];
    const float* fo_item  = (const float*)d_in[9];
    const float* fo_gender= (const float*)d_in[10];
    const float* fo_age   = (const float*)d_in[11];
    const float* fo_occ   = (const float*)d_in[12];
    const float* fo_genre = (const float*)d_in[13];
    const float* emb_user = (const float*)d_in[14];
    const float* emb_item = (const float*)d_in[15];
    const float* emb_gender=(const float*)d_in[16];
    const float* emb_age  = (const float*)d_in[17];
    const float* emb_occ  = (const float*)d_in[18];
    const float* emb_genre= (const float*)d_in[19];
    const float* dense_W  = (const float*)d_in[20];
    const float* dense_b  = (const float*)d_in[21];
    const float* W1       = (const float*)d_in[22];
    const float* b1       = (const float*)d_in[23];
    const float* W2       = (const float*)d_in[24];
    const float* b2       = (const float*)d_in[25];
    const float* Wout     = (const float*)d_in[26];
    const float* bout     = (const float*)d_in[27];
    float*       out      = (float*)d_out;

    const int B = in_sizes[0];
    const size_t smem = SMEM_FLOATS * sizeof(float);

    cudaFuncSetAttribute(deepfm_fused_kernel,
                         cudaFuncAttributeMaxDynamicSharedMemorySize, (int)smem);

    const int blocks = (B + TILE_R - 1) / TILE_R;
    deepfm_fused_kernel<<<blocks, 256, smem>>>(
        uid, iid, gen, age, occ, gids, gmask, dense,
        fo_user, fo_item, fo_gender, fo_age, fo_occ, fo_genre,
        emb_user, emb_item, emb_gender, emb_age, emb_occ, emb_genre,
        dense_W, dense_b, W1, b1, W2, b2, Wout, bout, out, B);
}

// round 3
// speedup vs baseline: 1.5171x; 1.1722x over previous
#include <cuda_runtime.h>
#include <cuda_bf16.h>

#define DEEP_IN 200
#define TILE_R  128

// Dynamic shared layout (floats):
//   Xs  : [128 r][200 k]         off 0       size 25600
//   h1s : [128 k][132 r]         off 25600   size 16896
//   WB0 : W1 chunk [40 k][132 j] off 42496   size 5280
//   WB1 : W1 chunk (buf 2)       off 47776   size 5280
//   W2S : [128 k][68 j]          off 42496   (reuses WB0+WB1 region)
#define OFF_XS   0
#define OFF_H1S  25600
#define OFF_WB0  42496
#define OFF_WB1  47776
#define OFF_W2S  42496
#define SMEM_FLOATS 53056   // 212224 bytes

__device__ __forceinline__ void stage_w1_chunk(float* __restrict__ dst,
                                               const float* __restrict__ W1,
                                               int c, int t)
{
    // chunk = W1[j][c*40 .. c*40+39] transposed -> dst[i*132 + j]
    const int j = t >> 2;        // 0..127
    const int q = t & 3;         // 0..3, each covers 10 k
    const float* src = W1 + j * DEEP_IN + c * 40 + q * 10;
#pragma unroll
    for (int s = 0; s < 5; s++) {
        const float2 v = *(const float2*)(src + s * 2);
        const int i = q * 10 + s * 2;
        dst[(i + 0) * 132 + j] = v.x;
        dst[(i + 1) * 132 + j] = v.y;
    }
}

__global__ __launch_bounds__(512, 1) void deepfm_fused_kernel(
    const int* __restrict__ uid, const int* __restrict__ iid,
    const int* __restrict__ gen, const int* __restrict__ age,
    const int* __restrict__ occ,
    const int* __restrict__ gids, const float* __restrict__ gmask,
    const float* __restrict__ dense,
    const float* __restrict__ fo_user, const float* __restrict__ fo_item,
    const float* __restrict__ fo_gender, const float* __restrict__ fo_age,
    const float* __restrict__ fo_occ, const float* __restrict__ fo_genre,
    const float* __restrict__ emb_user, const float* __restrict__ emb_item,
    const float* __restrict__ emb_gender, const float* __restrict__ emb_age,
    const float* __restrict__ emb_occ, const float* __restrict__ emb_genre,
    const float* __restrict__ dense_W, const float* __restrict__ dense_b,
    const float* __restrict__ W1, const float* __restrict__ b1,
    const float* __restrict__ W2, const float* __restrict__ b2,
    const float* __restrict__ Wout, const float* __restrict__ bout,
    float* __restrict__ out, int B)
{
    extern __shared__ float sm[];
    __shared__ float base_s[TILE_R];
    __shared__ float wout_s[64];

    const int t    = threadIdx.x;
    const int tx   = t & 15;       // 16 column groups
    const int ty   = t >> 4;       // 32 row groups (4 rows each)
    const int lane = t & 31;
    const int wrp  = t >> 5;       // 16 warps
    const int rowbase = blockIdx.x * TILE_R;

    if (t < 64) wout_s[t] = Wout[t];

    // Fire off W1 chunk0 staging loads first (latency hidden behind gather)
    stage_w1_chunk(sm + OFF_WB0, W1, 0, t);

    // ============ Gather prologue: warp w handles rows w*8 .. w*8+7 =========
#pragma unroll
    for (int i = 0; i < 8; i++) {
        const int rl = wrp * 8 + i;
        const int r  = rowbase + rl;
        if (r >= B) continue;

        const int u  = uid[r];
        const int it = iid[r];
        const int g  = gen[r];
        const int a  = age[r];
        const int o  = occ[r];

        const float xu = emb_user  [u  * 32 + lane];
        const float xi = emb_item  [it * 32 + lane];
        const float xg = emb_gender[g  * 32 + lane];
        const float xa = emb_age   [a  * 32 + lane];
        const float xo = emb_occ   [o  * 32 + lane];

        float gsum = 0.f, msum = 0.f, fsum = 0.f;
#pragma unroll
        for (int k = 0; k < 6; k++) {
            const int   gid = gids [r * 6 + k];
            const float m   = gmask[r * 6 + k];
            gsum += m * emb_genre[gid * 32 + lane];
            msum += m;
            fsum += m * fo_genre[gid];
        }
        const float denom = fmaxf(msum, 1.0f);
        const float xge = gsum / denom;

        float* xs = sm + OFF_XS + rl * DEEP_IN;
        xs[lane]       = xu;
        xs[32 + lane]  = xi;
        xs[64 + lane]  = xg;
        xs[96 + lane]  = xa;
        xs[128 + lane] = xo;
        xs[160 + lane] = xge;
        float dv = 0.f;
        if (lane < 8) {
            dv = dense[r * 8 + lane];
            xs[192 + lane] = dv;
        }

        // FM second order (lane = dim) + dense-linear, single fused reduction
        const float s  = xu + xi + xg + xa + xo + xge;
        const float sq = xu*xu + xi*xi + xg*xg + xa*xa + xo*xo + xge*xge;
        float red = 0.5f * (s * s - sq);
        if (lane < 8) red += dv * dense_W[lane];
#pragma unroll
        for (int off = 16; off; off >>= 1)
            red += __shfl_xor_sync(0xffffffffu, red, off);

        if (lane == 0) {
            base_s[rl] = fo_user[u] + fo_item[it] + fo_gender[g] + fo_age[a]
                       + fo_occ[o] + fsum / denom + dense_b[0] + red;
        }
    }
    __syncthreads();

    // Column ownership for layer1 (4+4 split at distance 64)
    // Rows: R = ty*4 + p (consecutive)
    // ============ Layer 1: h1 = relu(X @ W1^T + b1), double-buffered ========
    float acc[4][8];
#pragma unroll
    for (int p = 0; p < 4; p++)
#pragma unroll
        for (int q = 0; q < 8; q++) acc[p][q] = 0.f;

    for (int c = 0; c < 5; c++) {
        if (c < 4)
            stage_w1_chunk(sm + ((c & 1) ? OFF_WB0 : OFF_WB1), W1, c + 1, t);
        const float* wb = sm + ((c & 1) ? OFF_WB1 : OFF_WB0);
        const float* xbase = sm + OFF_XS + (ty * 4) * DEEP_IN + c * 40;

#pragma unroll 2
        for (int i = 0; i < 40; i += 4) {
            float4 xa4[4];
#pragma unroll
            for (int p = 0; p < 4; p++)
                xa4[p] = *(const float4*)(xbase + p * DEEP_IN + i);
#pragma unroll
            for (int kk = 0; kk < 4; kk++) {
                const float4 bl = *(const float4*)&wb[(i + kk) * 132 + tx * 4];
                const float4 bh = *(const float4*)&wb[(i + kk) * 132 + 64 + tx * 4];
                const float bv[8] = {bl.x, bl.y, bl.z, bl.w, bh.x, bh.y, bh.z, bh.w};
#pragma unroll
                for (int p = 0; p < 4; p++) {
                    const float av = ((const float*)&xa4[p])[kk];
#pragma unroll
                    for (int q = 0; q < 8; q++)
                        acc[p][q] = fmaf(av, bv[q], acc[p][q]);
                }
            }
        }
        __syncthreads();
    }

    // Writeback h1 (k-major) with STS.128, and stage W2 transposed
    {
#pragma unroll
        for (int q = 0; q < 8; q++) {
            const int C = tx * 4 + (q & 3) + (q >> 2) * 64;
            const float b1v = b1[C];
            float4 v;
            v.x = fmaxf(acc[0][q] + b1v, 0.f);
            v.y = fmaxf(acc[1][q] + b1v, 0.f);
            v.z = fmaxf(acc[2][q] + b1v, 0.f);
            v.w = fmaxf(acc[3][q] + b1v, 0.f);
            *(float4*)&sm[OFF_H1S + C * 132 + ty * 4] = v;
        }
        // W2S[k][j] = W2[j][k]
        const int j = t >> 3;      // 0..63
        const int o = t & 7;       // each covers 16 k
        const float* src = W2 + j * 128 + o * 16;
        float* dst = sm + OFF_W2S;
#pragma unroll
        for (int s = 0; s < 4; s++) {
            const float4 v = *(const float4*)(src + s * 4);
            const int k = o * 16 + s * 4;
            dst[(k + 0) * 68 + j] = v.x;
            dst[(k + 1) * 68 + j] = v.y;
            dst[(k + 2) * 68 + j] = v.z;
            dst[(k + 3) * 68 + j] = v.w;
        }
    }
    __syncthreads();

    // ============ Layer 2: h2 = relu(h1 @ W2^T + b2) ========================
    // cols: tx*4 .. tx*4+3 ; rows: ty*4 + p
    float acc2[4][4];
#pragma unroll
    for (int p = 0; p < 4; p++)
#pragma unroll
        for (int q = 0; q < 4; q++) acc2[p][q] = 0.f;

#pragma unroll 4
    for (int k = 0; k < 128; k++) {
        const float4 av = *(const float4*)&sm[OFF_H1S + k * 132 + ty * 4];
        const float4 bv = *(const float4*)&sm[OFF_W2S + k * 68 + tx * 4];
        const float a[4] = {av.x, av.y, av.z, av.w};
        const float b[4] = {bv.x, bv.y, bv.z, bv.w};
#pragma unroll
        for (int p = 0; p < 4; p++)
#pragma unroll
            for (int q = 0; q < 4; q++)
                acc2[p][q] = fmaf(a[p], b[q], acc2[p][q]);
    }

    // ============ Output: out = base + relu(h2) @ Wout + bout ===============
    {
        const float4 b2v4  = *(const float4*)&b2[tx * 4];
        const float4 wo4   = *(const float4*)&wout_s[tx * 4];
        const float b2v[4] = {b2v4.x, b2v4.y, b2v4.z, b2v4.w};
        const float wo[4]  = {wo4.x, wo4.y, wo4.z, wo4.w};
        const float boutv  = bout[0];
#pragma unroll
        for (int p = 0; p < 4; p++) {
            float part = 0.f;
#pragma unroll
            for (int q = 0; q < 4; q++)
                part += fmaxf(acc2[p][q] + b2v[q], 0.f) * wo[q];
            // reduce across the 16 tx lanes (stays within half-warp: ty fixed)
#pragma unroll
            for (int off = 8; off; off >>= 1)
                part += __shfl_xor_sync(0xffffffffu, part, off);
            if (tx == 0) {
                const int rl = ty * 4 + p;
                const int r  = rowbase + rl;
                if (r < B) out[r] = base_s[rl] + part + boutv;
            }
        }
    }
}

// ---------------------------------------------------------------------------
extern "C" void kernel_launch(void* const* d_in, const int* in_sizes, int n_in,
                              void* d_out, int out_size)
{
    const int*   uid      = (const int*)  d_in[0];
    const int*   iid      = (const int*)  d_in[1];
    const int*   gen      = (const int*)  d_in[2];
    const int*   age      = (const int*)  d_in[3];
    const int*   occ      = (const int*)  d_in[4];
    const int*   gids     = (const int*)  d_in[5];
    const float* gmask    = (const float*)d_in[6];
    const float* dense    = (const float*)d_in[7];
    const float* fo_user  = (const float*)d_in[8];
    const float* fo_item  = (const float*)d_in[9];
    const float* fo_gender= (const float*)d_in[10];
    const float* fo_age   = (const float*)d_in[11];
    const float* fo_occ   = (const float*)d_in[12];
    const float* fo_genre = (const float*)d_in[13];
    const float* emb_user = (const float*)d_in[14];
    const float* emb_item = (const float*)d_in[15];
    const float* emb_gender=(const float*)d_in[16];
    const float* emb_age  = (const float*)d_in[17];
    const float* emb_occ  = (const float*)d_in[18];
    const float* emb_genre= (const float*)d_in[19];
    const float* dense_W  = (const float*)d_in[20];
    const float* dense_b  = (const float*)d_in[21];
    const float* W1       = (const float*)d_in[22];
    const float* b1       = (const float*)d_in[23];
    const float* W2       = (const float*)d_in[24];
    const float* b2       = (const float*)d_in[25];
    const float* Wout     = (const float*)d_in[26];
    const float* bout     = (const float*)d_in[27];
    float*       out      = (float*)d_out;

    const int B = in_sizes[0];
    const size_t smem = SMEM_FLOATS * sizeof(float);

    cudaFuncSetAttribute(deepfm_fused_kernel,
                         cudaFuncAttributeMaxDynamicSharedMemorySize, (int)smem);

    const int blocks = (B + TILE_R - 1) / TILE_R;
    deepfm_fused_kernel<<<blocks, 512, smem>>>(
        uid, iid, gen, age, occ, gids, gmask, dense,
        fo_user, fo_item, fo_gender, fo_age, fo_occ, fo_genre,
        emb_user, emb_item, emb_gender, emb_age, emb_occ, emb_genre,
        dense_W, dense_b, W1, b1, W2, b2, Wout, bout, out, B);
}

// round 7
// speedup vs baseline: 1.9532x; 1.2874x over previous
#include <cuda_runtime.h>
#include <cuda_bf16.h>
#include <stdint.h>

#define DEEP_IN 200
#define TILE_R  128

// element strides (bf16) for padded row-major smem tiles
#define SX 216   // X / W1 rows (K padded 200->208, stride 216 => conflict-free ldmatrix)
#define SH 136   // h1 / W2 rows (K=128, stride 136)

// byte offsets in dynamic smem
#define XHI   0                    // X hi  [128][216]  (55296 B)
#define XLO   55296                // X lo
#define W1HI  110592               // W1 hi [128][216]
#define W1LO  165888               // W1 lo            -> total 221184
// reuse after layer 1:
#define H1HI  0                    // h1 hi [128][136] (34816 B)
#define H1LO  34816                // h1 lo
#define W2HI  110592               // W2 hi [64][136]  (17408 B)
#define W2LO  128000               // W2 lo
#define SMEM_BYTES 221184

__device__ __forceinline__ uint32_t smem_u32(const void* p) {
    uint32_t a;
    asm("{ .reg .u64 t; cvta.to.shared.u64 t, %1; cvt.u32.u64 %0, t; }"
        : "=r"(a) : "l"(p));
    return a;
}

#define LDMX4(r, addr) \
    asm volatile("ldmatrix.sync.aligned.m8n8.x4.shared.b16 {%0,%1,%2,%3}, [%4];" \
        : "=r"((r)[0]), "=r"((r)[1]), "=r"((r)[2]), "=r"((r)[3]) : "r"(addr))

#define MMA_BF16(d, a, b0, b1) \
    asm volatile("mma.sync.aligned.m16n8k16.row.col.f32.bf16.bf16.f32 " \
        "{%0,%1,%2,%3}, {%4,%5,%6,%7}, {%8,%9}, {%0,%1,%2,%3};" \
        : "+f"((d)[0]), "+f"((d)[1]), "+f"((d)[2]), "+f"((d)[3]) \
        : "r"((a)[0]), "r"((a)[1]), "r"((a)[2]), "r"((a)[3]), "r"(b0), "r"(b1))

__device__ __forceinline__ void store_split(char* hi, char* lo, uint32_t off, float x) {
    __nv_bfloat16 h = __float2bfloat16(x);
    __nv_bfloat16 l = __float2bfloat16(x - __bfloat162float(h));
    *(__nv_bfloat16*)(hi + off) = h;
    *(__nv_bfloat16*)(lo + off) = l;
}
__device__ __forceinline__ uint32_t packbf(float v0, float v1) {
    __nv_bfloat162 p = __floats2bfloat162_rn(v0, v1);
    return *(uint32_t*)&p;
}
// split pair (v0,v1) into hi/lo bf16x2 words and store
__device__ __forceinline__ void store_split2(char* hi, char* lo, uint32_t off,
                                             float v0, float v1) {
    __nv_bfloat16 h0 = __float2bfloat16(v0), h1 = __float2bfloat16(v1);
    float l0 = v0 - __bfloat162float(h0), l1 = v1 - __bfloat162float(h1);
    *(uint32_t*)(hi + off) = packbf(__bfloat162float(h0), __bfloat162float(h1));
    *(uint32_t*)(lo + off) = packbf(l0, l1);
}

__global__ __launch_bounds__(512, 1) void deepfm_hmma_kernel(
    const int* __restrict__ uid, const int* __restrict__ iid,
    const int* __restrict__ gen, const int* __restrict__ age,
    const int* __restrict__ occ,
    const int* __restrict__ gids, const float* __restrict__ gmask,
    const float* __restrict__ dense,
    const float* __restrict__ fo_user, const float* __restrict__ fo_item,
    const float* __restrict__ fo_gender, const float* __restrict__ fo_age,
    const float* __restrict__ fo_occ, const float* __restrict__ fo_genre,
    const float* __restrict__ emb_user, const float* __restrict__ emb_item,
    const float* __restrict__ emb_gender, const float* __restrict__ emb_age,
    const float* __restrict__ emb_occ, const float* __restrict__ emb_genre,
    const float* __restrict__ dense_W, const float* __restrict__ dense_b,
    const float* __restrict__ W1, const float* __restrict__ b1,
    const float* __restrict__ W2, const float* __restrict__ b2,
    const float* __restrict__ Wout, const float* __restrict__ bout,
    float* __restrict__ out, int B)
{
    extern __shared__ char sm[];
    __shared__ float base_s[TILE_R];
    __shared__ float b1s[128], b2s[64], wouts[64];
    __shared__ float part[4][128];

    const int t    = threadIdx.x;
    const int lane = t & 31;
    const int wrp  = t >> 5;
    const int rowbase = blockIdx.x * TILE_R;
    const uint32_t smb = smem_u32(sm);

    if (t < 128)      b1s[t] = b1[t];
    else if (t < 192) b2s[t - 128] = b2[t - 128];
    else if (t < 256) wouts[t - 192] = Wout[t - 192];

    // ---- stage W1 (fp32 -> bf16 hi/lo), 4 threads per row, float2 loads ----
    {
        const int j = t >> 2, q = t & 3;
        const float* src = W1 + j * DEEP_IN + q * 50;
        const uint32_t rb = j * (SX * 2) + q * 100;   // byte offset of k = q*50
#pragma unroll
        for (int s = 0; s < 25; s++) {
            const float2 v = *(const float2*)(src + s * 2);
            store_split2(sm + W1HI, sm + W1LO, rb + s * 4, v.x, v.y);
        }
    }
    // ---- zero pads k=200..207 for X and W1 ---------------------------------
    for (int e = t; e < 128 * 8; e += 512) {
        const int r = e >> 3, k = 200 + (e & 7);
        const uint32_t o = (r * SX + k) * 2;
        *(__nv_bfloat16*)(sm + XHI  + o) = __float2bfloat16(0.f);
        *(__nv_bfloat16*)(sm + XLO  + o) = __float2bfloat16(0.f);
        *(__nv_bfloat16*)(sm + W1HI + o) = __float2bfloat16(0.f);
        *(__nv_bfloat16*)(sm + W1LO + o) = __float2bfloat16(0.f);
    }

    // ---- gather: warp w -> rows w*8..w*8+7, exact fp32 FM terms ------------
#pragma unroll
    for (int i = 0; i < 8; i++) {
        const int rl = wrp * 8 + i;
        const int r  = rowbase + rl;
        if (r >= B) continue;

        const int u  = uid[r];
        const int it = iid[r];
        const int g  = gen[r];
        const int a  = age[r];
        const int o  = occ[r];

        const float xu = emb_user  [u  * 32 + lane];
        const float xi = emb_item  [it * 32 + lane];
        const float xg = emb_gender[g  * 32 + lane];
        const float xa = emb_age   [a  * 32 + lane];
        const float xo = emb_occ   [o  * 32 + lane];

        float gsum = 0.f, msum = 0.f, fsum = 0.f;
#pragma unroll
        for (int k = 0; k < 6; k++) {
            const int   gid = gids [r * 6 + k];
            const float m   = gmask[r * 6 + k];
            gsum += m * emb_genre[gid * 32 + lane];
            msum += m;
            fsum += m * fo_genre[gid];
        }
        const float denom = fmaxf(msum, 1.0f);
        const float xge = gsum / denom;

        const uint32_t rb = rl * (SX * 2);
        store_split(sm + XHI, sm + XLO, rb + (lane) * 2,        xu);
        store_split(sm + XHI, sm + XLO, rb + (32 + lane) * 2,   xi);
        store_split(sm + XHI, sm + XLO, rb + (64 + lane) * 2,   xg);
        store_split(sm + XHI, sm + XLO, rb + (96 + lane) * 2,   xa);
        store_split(sm + XHI, sm + XLO, rb + (128 + lane) * 2,  xo);
        store_split(sm + XHI, sm + XLO, rb + (160 + lane) * 2,  xge);
        float dv = 0.f;
        if (lane < 8) {
            dv = dense[r * 8 + lane];
            store_split(sm + XHI, sm + XLO, rb + (192 + lane) * 2, dv);
        }

        const float s  = xu + xi + xg + xa + xo + xge;
        const float sq = xu*xu + xi*xi + xg*xg + xa*xa + xo*xo + xge*xge;
        float red = 0.5f * (s * s - sq);
        if (lane < 8) red += dv * dense_W[lane];
#pragma unroll
        for (int off = 16; off; off >>= 1)
            red += __shfl_xor_sync(0xffffffffu, red, off);
        if (lane == 0)
            base_s[rl] = fo_user[u] + fo_item[it] + fo_gender[g] + fo_age[a]
                       + fo_occ[o] + fsum / denom + dense_b[0] + red;
    }
    __syncthreads();

    // ======================= Layer 1: 128x128x208 ===========================
    // warp (wm, wn) computes rows wm*32..+31, cols wn*32..+31
    const int wm = wrp >> 2;
    {
        const int wn = wrp & 3;
        float d[2][4][4];
#pragma unroll
        for (int r = 0; r < 2; r++)
#pragma unroll
            for (int nb = 0; nb < 4; nb++)
#pragma unroll
                for (int c = 0; c < 4; c++) d[r][nb][c] = 0.f;

        // invariant ldmatrix lane addresses (byte offsets), k advances by 32 B
        uint32_t aAddr[2], bAddr[2];
#pragma unroll
        for (int r = 0; r < 2; r++)
            aAddr[r] = smb + (uint32_t)((wm * 32 + r * 16 + (lane & 15)) * (SX * 2)
                     + (lane >> 4) * 16);
#pragma unroll
        for (int h = 0; h < 2; h++)
            bAddr[h] = smb + W1HI
                     + (uint32_t)((wn * 32 + h * 16 + ((lane >> 4) << 3) + (lane & 7)) * (SX * 2)
                     + ((lane >> 3) & 1) * 16);

        for (int ks = 0; ks < 13; ks++) {
            const uint32_t kb = ks * 32;
            uint32_t ah[2][4], al[2][4], bh[2][4], bl[2][4];
#pragma unroll
            for (int r = 0; r < 2; r++) {
                LDMX4(ah[r], aAddr[r] + XHI + kb);
                LDMX4(al[r], aAddr[r] + XLO + kb);
            }
#pragma unroll
            for (int h = 0; h < 2; h++) {
                LDMX4(bh[h], bAddr[h] + kb);
                LDMX4(bl[h], bAddr[h] + (W1LO - W1HI) + kb);
            }
#pragma unroll
            for (int r = 0; r < 2; r++)
#pragma unroll
                for (int h = 0; h < 2; h++)
#pragma unroll
                    for (int hf = 0; hf < 2; hf++) {
                        const int nb = h * 2 + hf;
                        MMA_BF16(d[r][nb], ah[r], bh[h][hf*2], bh[h][hf*2+1]);
                        MMA_BF16(d[r][nb], ah[r], bl[h][hf*2], bl[h][hf*2+1]);
                        MMA_BF16(d[r][nb], al[r], bh[h][hf*2], bh[h][hf*2+1]);
                    }
        }
        __syncthreads();   // all reads of X/W1 done before overwrite

        // epilogue: relu(d + b1) -> h1 hi/lo [m][k] stride SH
#pragma unroll
        for (int r = 0; r < 2; r++)
#pragma unroll
            for (int nb = 0; nb < 4; nb++) {
                const int n = wn * 32 + nb * 8 + 2 * (lane & 3);
                const int m0 = wm * 32 + r * 16 + (lane >> 2);
                const float v0 = fmaxf(d[r][nb][0] + b1s[n], 0.f);
                const float v1 = fmaxf(d[r][nb][1] + b1s[n + 1], 0.f);
                store_split2(sm + H1HI, sm + H1LO, (m0 * SH + n) * 2, v0, v1);
                const float v2 = fmaxf(d[r][nb][2] + b1s[n], 0.f);
                const float v3 = fmaxf(d[r][nb][3] + b1s[n + 1], 0.f);
                store_split2(sm + H1HI, sm + H1LO, ((m0 + 8) * SH + n) * 2, v2, v3);
            }
    }
    // stage W2 [64][128] -> hi/lo stride SH
    for (int e = t; e < 64 * 32; e += 512) {
        const int j = e >> 5, q = e & 31;       // 32 float4 per row
        const float4 v = *(const float4*)(W2 + j * 128 + q * 4);
        const uint32_t o = (j * SH + q * 4) * 2;
        store_split2(sm + W2HI, sm + W2LO, o,     v.x, v.y);
        store_split2(sm + W2HI, sm + W2LO, o + 4, v.z, v.w);
    }
    __syncthreads();

    // ======================= Layer 2: 128x64x128 ============================
    {
        const int wn2 = wrp & 3;                // 16 cols each
        float d2[2][2][4];
#pragma unroll
        for (int r = 0; r < 2; r++)
#pragma unroll
            for (int nb = 0; nb < 2; nb++)
#pragma unroll
                for (int c = 0; c < 4; c++) d2[r][nb][c] = 0.f;

        uint32_t aAddr[2];
#pragma unroll
        for (int r = 0; r < 2; r++)
            aAddr[r] = smb + (uint32_t)((wm * 32 + r * 16 + (lane & 15)) * (SH * 2)
                     + (lane >> 4) * 16);
        const uint32_t bAddr = smb + W2HI
                     + (uint32_t)((wn2 * 16 + ((lane >> 4) << 3) + (lane & 7)) * (SH * 2)
                     + ((lane >> 3) & 1) * 16);

#pragma unroll
        for (int ks = 0; ks < 8; ks++) {
            const uint32_t kb = ks * 32;
            uint32_t ah[2][4], al[2][4], bh[4], bl[4];
#pragma unroll
            for (int r = 0; r < 2; r++) {
                LDMX4(ah[r], aAddr[r] + H1HI + kb);
                LDMX4(al[r], aAddr[r] + H1LO + kb);
            }
            LDMX4(bh, bAddr + kb);
            LDMX4(bl, bAddr + (W2LO - W2HI) + kb);
#pragma unroll
            for (int r = 0; r < 2; r++)
#pragma unroll
                for (int hf = 0; hf < 2; hf++) {
                    MMA_BF16(d2[r][hf], ah[r], bh[hf*2], bh[hf*2+1]);
                    MMA_BF16(d2[r][hf], ah[r], bl[hf*2], bl[hf*2+1]);
                    MMA_BF16(d2[r][hf], al[r], bh[hf*2], bh[hf*2+1]);
                }
        }

        // epilogue 2: relu(d2 + b2) . wout, quad-reduce, partials to smem
#pragma unroll
        for (int r = 0; r < 2; r++) {
            float s_lo = 0.f, s_hi = 0.f;
#pragma unroll
            for (int nb = 0; nb < 2; nb++) {
                const int n = wn2 * 16 + nb * 8 + 2 * (lane & 3);
                s_lo += fmaxf(d2[r][nb][0] + b2s[n], 0.f)     * wouts[n]
                      + fmaxf(d2[r][nb][1] + b2s[n + 1], 0.f) * wouts[n + 1];
                s_hi += fmaxf(d2[r][nb][2] + b2s[n], 0.f)     * wouts[n]
                      + fmaxf(d2[r][nb][3] + b2s[n + 1], 0.f) * wouts[n + 1];
            }
#pragma unroll
            for (int off = 1; off <= 2; off <<= 1) {
                s_lo += __shfl_xor_sync(0xffffffffu, s_lo, off);
                s_hi += __shfl_xor_sync(0xffffffffu, s_hi, off);
            }
            if ((lane & 3) == 0) {
                const int m0 = wm * 32 + r * 16 + (lane >> 2);
                part[wn2][m0]     = s_lo;
                part[wn2][m0 + 8] = s_hi;
            }
        }
    }
    __syncthreads();

    if (t < 128) {
        const int r = rowbase + t;
        if (r < B)
            out[r] = base_s[t] + part[0][t] + part[1][t] + part[2][t] + part[3][t]
                   + bout[0];
    }
}

// ---------------------------------------------------------------------------
extern "C" void kernel_launch(void* const* d_in, const int* in_sizes, int n_in,
                              void* d_out, int out_size)
{
    const int*   uid      = (const int*)  d_in[0];
    const int*   iid      = (const int*)  d_in[1];
    const int*   gen      = (const int*)  d_in[2];
    const int*   age      = (const int*)  d_in[3];
    const int*   occ      = (const int*)  d_in[4];
    const int*   gids     = (const int*)  d_in[5];
    const float* gmask    = (const float*)d_in[6];
    const float* dense    = (const float*)d_in[7];
    const float* fo_user  = (const float*)d_in[8];
    const float* fo_item  = (const float*)d_in[9];
    const float* fo_gender= (const float*)d_in[10];
    const float* fo_age   = (const float*)d_in[11];
    const float* fo_occ   = (const float*)d_in[12];
    const float* fo_genre = (const float*)d_in[13];
    const float* emb_user = (const float*)d_in[14];
    const float* emb_item = (const float*)d_in[15];
    const float* emb_gender=(const float*)d_in[16];
    const float* emb_age  = (const float*)d_in[17];
    const float* emb_occ  = (const float*)d_in[18];
    const float* emb_genre= (const float*)d_in[19];
    const float* dense_W  = (const float*)d_in[20];
    const float* dense_b  = (const float*)d_in[21];
    const float* W1       = (const float*)d_in[22];
    const float* b1       = (const float*)d_in[23];
    const float* W2       = (const float*)d_in[24];
    const float* b2       = (const float*)d_in[25];
    const float* Wout     = (const float*)d_in[26];
    const float* bout     = (const float*)d_in[27];
    float*       out      = (float*)d_out;

    const int B = in_sizes[0];

    cudaFuncSetAttribute(deepfm_hmma_kernel,
                         cudaFuncAttributeMaxDynamicSharedMemorySize, SMEM_BYTES);

    const int blocks = (B + TILE_R - 1) / TILE_R;
    deepfm_hmma_kernel<<<blocks, 512, SMEM_BYTES>>>(
        uid, iid, gen, age, occ, gids, gmask, dense,
        fo_user, fo_item, fo_gender, fo_age, fo_occ, fo_genre,
        emb_user, emb_item, emb_gender, emb_age, emb_occ, emb_genre,
        dense_W, dense_b, W1, b1, W2, b2, Wout, bout, out, B);
}